// round 15
// baseline (speedup 1.0000x reference)
#include <cuda_runtime.h>
#include <cuda_fp16.h>
#include <cstdint>
#include <math.h>

// ConvergedInhibition == circular deconvolution along C=128 channels.
// Y = G @ X, G[r][j] = g[(r-j)&127], g = ifft(1/fft(delta-k)).
// R15: R14 + warp tile 64m x 8n -> ldsm.x2 (halves B smem re-reads),
//      identity column layout (permutation deleted; lane cols naturally
//      contiguous). In-kernel prep, depth-2 reordered cp.async pipeline,
//      512 threads, <=64 regs, 2 CTAs/SM, single-pass fp16 mma.

#define CCH     128
#define HWSZ    4096
#define NBATCH  64
#define SCOPE   27
#define NTILE_N 64
#define NTHREADS 512
#define NTILES_TOTAL (NBATCH * (HWSZ / NTILE_N))   // 4096

#define SPITCH_B 272                    // staging row: 64 fp32 + 16B pad
#define STAGE_B  (CCH * SPITCH_B)       // 34816
#define XPITCH_B 272                    // fp16 row: 128 fp16 + 16B pad
#define F16_B    (NTILE_N * XPITCH_B)   // 17408
#define SMEM_S0  0
#define SMEM_S1  STAGE_B
#define SMEM_F0  (2 * STAGE_B)          // 69632
#define SMEM_F1  (2 * STAGE_B + F16_B)  // 87040
#define SMEM_DYN (2 * STAGE_B + 2 * F16_B)  // 104448

// ---------------------------------------------------------------------------
__device__ __forceinline__ uint32_t s2u(const void* p) {
    uint32_t a;
    asm("{ .reg .u64 t; cvta.to.shared.u64 t, %1; cvt.u32.u64 %0, t; }"
        : "=r"(a) : "l"(p));
    return a;
}
__device__ __forceinline__ uint32_t pack_f16x2(float lo, float hi) {
    uint32_t r;
    asm("cvt.rn.f16x2.f32 %0, %1, %2;" : "=r"(r) : "f"(hi), "f"(lo));
    return r;
}
__device__ __forceinline__ void cp_async16(uint32_t dst, const void* src) {
    asm volatile("cp.async.cg.shared.global [%0], [%1], 16;"
                 :: "r"(dst), "l"(src) : "memory");
}
__device__ __forceinline__ void cp_commit() {
    asm volatile("cp.async.commit_group;" ::: "memory");
}
__device__ __forceinline__ void cp_wait0() {
    asm volatile("cp.async.wait_group 0;" ::: "memory");
}
__device__ __forceinline__ void cp_wait1() {
    asm volatile("cp.async.wait_group 1;" ::: "memory");
}
__device__ __forceinline__ void ldsm_x2(uint32_t& r0, uint32_t& r1, uint32_t a) {
    asm volatile("ldmatrix.sync.aligned.m8n8.x2.shared.b16 {%0,%1}, [%2];"
                 : "=r"(r0), "=r"(r1) : "r"(a));
}
__device__ __forceinline__ void mma16816(float* c, uint32_t ax, uint32_t ay,
                                         uint32_t az, uint32_t b0, uint32_t b1) {
    asm volatile(
        "mma.sync.aligned.m16n8k16.row.col.f32.f16.f16.f32 "
        "{%0,%1,%2,%3}, {%4,%5,%6,%4}, {%7,%8}, {%0,%1,%2,%3};"
        : "+f"(c[0]), "+f"(c[1]), "+f"(c[2]), "+f"(c[3])
        : "r"(ax), "r"(ay), "r"(az), "r"(b0), "r"(b1));
}

// ---------------------------------------------------------------------------
// Persistent staged GEMM, 512 threads, in-kernel prep.
// Tile = 128m x 64n. 16 warps: warp_m = wid&1 (64 rows), warp_n = wid>>1 (8).
// ---------------------------------------------------------------------------
__global__ void __launch_bounds__(NTHREADS, 2)
gemm_mma(const float* __restrict__ x, const float* __restrict__ filt,
         float* __restrict__ y) {
    extern __shared__ char smc[];
    __shared__ float tw_re[CCH], tw_im[CCH];
    __shared__ float inv_re[CCH], inv_im[CCH];
    __shared__ float ft[SCOPE];
    __shared__ float g_s[CCH];

    const int tid  = threadIdx.x;
    const int wid  = tid >> 5;
    const int lane = tid & 31;
    const int warp_m = wid & 1;
    const int warp_n = wid >> 1;

    const uint32_t smb = s2u(smc);

    int tile = blockIdx.x;
    if (tile >= NTILES_TOTAL) return;
    const int stride = gridDim.x;

#define STAGE_TILE(tt, sb)                                                   \
    do {                                                                     \
        const float* xb_ = x + (size_t)((tt) >> 6) * CCH * HWSZ              \
                             + ((tt) & 63) * NTILE_N;                        \
        _Pragma("unroll")                                                    \
        for (int i_ = 0; i_ < 4; i_++) {                                     \
            int c_ = tid + NTHREADS * i_;                                    \
            int k_ = c_ >> 4, n4_ = c_ & 15;                                 \
            cp_async16((sb) + k_ * SPITCH_B + n4_ * 16,                      \
                       xb_ + (size_t)k_ * HWSZ + n4_ * 4);                   \
        }                                                                    \
    } while (0)

    // ---- stage tile0 FIRST: its DRAM latency covers the g computation ----
    STAGE_TILE(tile, smb + SMEM_S0);
    cp_commit();                       // group: t0

    // ---- in-CTA prep: g = real(ifft(1/fft(delta - k_rolled))) ----
    if (tid < SCOPE) ft[tid] = filt[tid];
    if (tid < CCH) {
        float s, c;
        sincosf(6.283185307179586f * (float)tid / 128.0f, &s, &c);
        tw_re[tid] = c; tw_im[tid] = s;
    }
    __syncthreads();
    if (tid < CCH) {
        float fr = 1.0f, fi = 0.0f;
#pragma unroll
        for (int j = 0; j < SCOPE; j++) {
            int p = (115 + j) & 127;
            int idx = (tid * p) & 127;
            fr -= ft[j] * tw_re[idx];
            fi += ft[j] * tw_im[idx];
        }
        float d = fr * fr + fi * fi;
        inv_re[tid] = fr / d; inv_im[tid] = -fi / d;
    }
    __syncthreads();
    if (tid < CCH) {
        float acc = 0.0f;
        for (int f = 0; f < CCH; f++) {
            int idx = (f * tid) & 127;
            acc += tw_re[idx] * inv_re[f] - tw_im[idx] * inv_im[f];
        }
        g_s[tid] = acc * (1.0f / 128.0f);
    }
    __syncthreads();

    // ---- A fragments from g_s: 8 diagonal classes, 3 words (w == x) ----
    // warp covers 64 rows (4 mtiles); class index (warp_m*4 + mt - ks)&7.
    uint32_t ax[8], ay[8], az[8];
#pragma unroll
    for (int i = 0; i < 8; i++) {
        int cls = ((warp_m * 4) + i) & 7;
        int d0 = (16 * cls + (lane >> 2) - 2 * (lane & 3)) & 127;
        ax[i] = pack_f16x2(g_s[d0], g_s[(d0 - 1) & 127]);
        int d1 = (d0 + 8) & 127;
        ay[i] = pack_f16x2(g_s[d1], g_s[(d1 - 1) & 127]);
        int d2 = (d0 - 8) & 127;
        az[i] = pack_f16x2(g_s[d2], g_s[(d2 - 1) & 127]);
    }

    // convert constants: thread -> (n-row n0, k-eighth kq); identity cols
    const int n0 = tid & 63;
    const int kq = tid >> 6;                 // 0..7 (16 k's each)

    // ldsm.x2 constants (fp16 buf rows = n, 64 rows, pitch 272):
    // lanes 0-7 -> matrix0 rows n (khalf 0), lanes 8-15 -> matrix1 (khalf 1)
    const uint32_t lm_off = (lane & 7) * XPITCH_B + ((lane >> 3) & 1) * 16
                          + (uint32_t)warp_n * 8 * XPITCH_B;

#define CONVERT_TILE(soff, foff)                                             \
    do {                                                                     \
        const char* sk_ = smc + (soff) + n0 * 4                              \
                        + (size_t)(kq * 16) * SPITCH_B;                      \
        char* dk_ = smc + (foff) + (uint32_t)n0 * XPITCH_B + kq * 32;        \
        _Pragma("unroll")                                                    \
        for (int ch_ = 0; ch_ < 2; ch_++) {                                  \
            float v_[8];                                                     \
            _Pragma("unroll")                                                \
            for (int ii_ = 0; ii_ < 8; ii_++)                                \
                v_[ii_] = *reinterpret_cast<const float*>(                   \
                    sk_ + (size_t)(ch_ * 8 + ii_) * SPITCH_B);               \
            uint4 hq_;                                                       \
            hq_.x = pack_f16x2(v_[0], v_[1]);                                \
            hq_.y = pack_f16x2(v_[2], v_[3]);                                \
            hq_.z = pack_f16x2(v_[4], v_[5]);                                \
            hq_.w = pack_f16x2(v_[6], v_[7]);                                \
            *reinterpret_cast<uint4*>(dk_ + ch_ * 16) = hq_;                 \
        }                                                                    \
    } while (0)

    // ---- prologue (continues): convert tile0, stage tile1 ----
    cp_wait0();
    __syncthreads();
    CONVERT_TILE(SMEM_S0, SMEM_F0);    // f16[0] = tile0
    __syncthreads();                   // stg0 reads done; f16[0] visible
    {
        const int t1 = tile + stride;
        if (t1 < NTILES_TOTAL) STAGE_TILE(t1, smb + SMEM_S1);
        cp_commit();                   // group: t1
    }

    int par = 0;
    // invariant at loop top: f16[par] = tile t (all warps see it);
    // stg[par^1] carries cp(t+1); stg[par] free.
    for (; tile < NTILES_TOTAL; tile += stride, par ^= 1) {
        // 1. issue cp(t+2) into the free staging buffer
        {
            const int n2 = tile + 2 * stride;
            if (n2 < NTILES_TOTAL)
                STAGE_TILE(n2, smb + (par ? SMEM_S1 : SMEM_S0));
            cp_commit();
        }

        // 2. mma(t) from f16[par] + epilogue (covers cp(t+1), cp(t+2))
        {
            const uint32_t xh_base = smb + (par ? SMEM_F1 : SMEM_F0) + lm_off;
            float acc[4][4];
#pragma unroll
            for (int mt = 0; mt < 4; mt++)
#pragma unroll
                for (int r = 0; r < 4; r++) acc[mt][r] = 0.0f;

#pragma unroll
            for (int ks = 0; ks < 8; ks++) {
                uint32_t b0, b1;
                ldsm_x2(b0, b1, xh_base + (uint32_t)ks * 32);
#pragma unroll
                for (int mt = 0; mt < 4; mt++) {
                    const int ai = (mt - ks) & 7;
                    mma16816(acc[mt], ax[ai], ay[ai], az[ai], b0, b1);
                }
            }

            // epilogue: lane holds cols (2q, 2q+1) of rows m0, m0+8
            float* yb = y + (size_t)(tile >> 6) * CCH * HWSZ
                          + (tile & 63) * NTILE_N + warp_n * 8
                          + 2 * (lane & 3);
#pragma unroll
            for (int mt = 0; mt < 4; mt++) {
                int m0 = warp_m * 64 + mt * 16 + (lane >> 2);
                *reinterpret_cast<float2*>(yb + (size_t)m0 * HWSZ) =
                    make_float2(acc[mt][0], acc[mt][1]);
                *reinterpret_cast<float2*>(yb + (size_t)(m0 + 8) * HWSZ) =
                    make_float2(acc[mt][2], acc[mt][3]);
            }
        }

        // 3. cp(t+1) landed; make visible to all warps
        cp_wait1();
        __syncthreads();

        // 4. convert(t+1): stg[par^1] -> f16[par^1]
        if (tile + stride < NTILES_TOTAL) {
            if (par) CONVERT_TILE(SMEM_S0, SMEM_F0);
            else     CONVERT_TILE(SMEM_S1, SMEM_F1);
        }
        __syncthreads();   // f16[par^1] ready; stg[par^1] reads done
    }
#undef STAGE_TILE
#undef CONVERT_TILE
}

// ---------------------------------------------------------------------------
extern "C" void kernel_launch(void* const* d_in, const int* in_sizes, int n_in,
                              void* d_out, int out_size) {
    const float* act  = (const float*)d_in[0];
    const float* filt = (const float*)d_in[1];
    if (n_in >= 2 && in_sizes[0] == SCOPE) {
        act  = (const float*)d_in[1];
        filt = (const float*)d_in[0];
    }
    float* out = (float*)d_out;

    int nsm = 148;
    cudaDeviceGetAttribute(&nsm, cudaDevAttrMultiProcessorCount, 0);
    int grid = 2 * nsm;
    if (grid > NTILES_TOTAL) grid = NTILES_TOTAL;

    cudaFuncSetAttribute(gemm_mma,
                         cudaFuncAttributeMaxDynamicSharedMemorySize, SMEM_DYN);
    gemm_mma<<<grid, NTHREADS, SMEM_DYN>>>(act, filt, out);
}

// round 16
// speedup vs baseline: 1.0390x; 1.0390x over previous
#include <cuda_runtime.h>
#include <cuda_fp16.h>
#include <cstdint>
#include <math.h>

// ConvergedInhibition == circular deconvolution along C=128 channels.
// Y = G @ X, G[r][j] = g[(r-j)&127], g = ifft(1/fft(delta-k)).
// R16: R14 base (best: 52.5us) + convert(t+1) FUSED into mma(t) k-loop
//      (convert reads staging smem that landed a tile ago -> no latency
//      to hide, just fills mma-phase issue slots; deletes the serial
//      convert phase). In-kernel prep, depth-2 cp.async, 512 threads,
//      <=64 regs, 2 CTAs/SM, single-pass fp16 mma, circulant A-frags,
//      permuted-column float4 epilogue.

#define CCH     128
#define HWSZ    4096
#define NBATCH  64
#define SCOPE   27
#define NTILE_N 64
#define NTHREADS 512
#define NTILES_TOTAL (NBATCH * (HWSZ / NTILE_N))   // 4096

#define SPITCH_B 272                    // staging row: 64 fp32 + 16B pad
#define STAGE_B  (CCH * SPITCH_B)       // 34816
#define XPITCH_B 272                    // fp16 row: 128 fp16 + 16B pad
#define F16_B    (NTILE_N * XPITCH_B)   // 17408
#define SMEM_S0  0
#define SMEM_S1  STAGE_B
#define SMEM_F0  (2 * STAGE_B)          // 69632
#define SMEM_F1  (2 * STAGE_B + F16_B)  // 87040
#define SMEM_DYN (2 * STAGE_B + 2 * F16_B)  // 104448

// ---------------------------------------------------------------------------
__device__ __forceinline__ uint32_t s2u(const void* p) {
    uint32_t a;
    asm("{ .reg .u64 t; cvta.to.shared.u64 t, %1; cvt.u32.u64 %0, t; }"
        : "=r"(a) : "l"(p));
    return a;
}
__device__ __forceinline__ uint32_t pack_f16x2(float lo, float hi) {
    uint32_t r;
    asm("cvt.rn.f16x2.f32 %0, %1, %2;" : "=r"(r) : "f"(hi), "f"(lo));
    return r;
}
__device__ __forceinline__ void cp_async16(uint32_t dst, const void* src) {
    asm volatile("cp.async.cg.shared.global [%0], [%1], 16;"
                 :: "r"(dst), "l"(src) : "memory");
}
__device__ __forceinline__ void cp_commit() {
    asm volatile("cp.async.commit_group;" ::: "memory");
}
__device__ __forceinline__ void cp_wait0() {
    asm volatile("cp.async.wait_group 0;" ::: "memory");
}
__device__ __forceinline__ void cp_wait1() {
    asm volatile("cp.async.wait_group 1;" ::: "memory");
}
__device__ __forceinline__ void ldsm_x4(uint32_t& r0, uint32_t& r1,
                                        uint32_t& r2, uint32_t& r3, uint32_t a) {
    asm volatile("ldmatrix.sync.aligned.m8n8.x4.shared.b16 {%0,%1,%2,%3}, [%4];"
                 : "=r"(r0), "=r"(r1), "=r"(r2), "=r"(r3) : "r"(a));
}
__device__ __forceinline__ void mma16816(float* c, uint32_t ax, uint32_t ay,
                                         uint32_t az, uint32_t b0, uint32_t b1) {
    asm volatile(
        "mma.sync.aligned.m16n8k16.row.col.f32.f16.f16.f32 "
        "{%0,%1,%2,%3}, {%4,%5,%6,%4}, {%7,%8}, {%0,%1,%2,%3};"
        : "+f"(c[0]), "+f"(c[1]), "+f"(c[2]), "+f"(c[3])
        : "r"(ax), "r"(ay), "r"(az), "r"(b0), "r"(b1));
}

// ---------------------------------------------------------------------------
// Persistent staged GEMM, 512 threads, in-kernel prep, fused convert.
// Tile = 128m x 64n. 16 warps: warp_m = wid&3 (32 rows), warp_n = wid>>2.
// ---------------------------------------------------------------------------
__global__ void __launch_bounds__(NTHREADS, 2)
gemm_mma(const float* __restrict__ x, const float* __restrict__ filt,
         float* __restrict__ y) {
    extern __shared__ char smc[];
    __shared__ float tw_re[CCH], tw_im[CCH];
    __shared__ float inv_re[CCH], inv_im[CCH];
    __shared__ float ft[SCOPE];
    __shared__ float g_s[CCH];

    const int tid  = threadIdx.x;
    const int wid  = tid >> 5;
    const int lane = tid & 31;
    const int warp_m = wid & 3;
    const int warp_n = wid >> 2;

    const uint32_t smb = s2u(smc);

    int tile = blockIdx.x;
    if (tile >= NTILES_TOTAL) return;
    const int stride = gridDim.x;

#define STAGE_TILE(tt, sb)                                                   \
    do {                                                                     \
        const float* xb_ = x + (size_t)((tt) >> 6) * CCH * HWSZ              \
                             + ((tt) & 63) * NTILE_N;                        \
        _Pragma("unroll")                                                    \
        for (int i_ = 0; i_ < 4; i_++) {                                     \
            int c_ = tid + NTHREADS * i_;                                    \
            int k_ = c_ >> 4, n4_ = c_ & 15;                                 \
            cp_async16((sb) + k_ * SPITCH_B + n4_ * 16,                      \
                       xb_ + (size_t)k_ * HWSZ + n4_ * 4);                   \
        }                                                                    \
    } while (0)

    // ---- stage tile0 FIRST: its DRAM latency covers the g computation ----
    STAGE_TILE(tile, smb + SMEM_S0);
    cp_commit();                       // group: t0

    // ---- in-CTA prep: g = real(ifft(1/fft(delta - k_rolled))) ----
    if (tid < SCOPE) ft[tid] = filt[tid];
    if (tid < CCH) {
        float s, c;
        sincosf(6.283185307179586f * (float)tid / 128.0f, &s, &c);
        tw_re[tid] = c; tw_im[tid] = s;
    }
    __syncthreads();
    if (tid < CCH) {
        float fr = 1.0f, fi = 0.0f;
#pragma unroll
        for (int j = 0; j < SCOPE; j++) {
            int p = (115 + j) & 127;
            int idx = (tid * p) & 127;
            fr -= ft[j] * tw_re[idx];
            fi += ft[j] * tw_im[idx];
        }
        float d = fr * fr + fi * fi;
        inv_re[tid] = fr / d; inv_im[tid] = -fi / d;
    }
    __syncthreads();
    if (tid < CCH) {
        float acc = 0.0f;
        for (int f = 0; f < CCH; f++) {
            int idx = (f * tid) & 127;
            acc += tw_re[idx] * inv_re[f] - tw_im[idx] * inv_im[f];
        }
        g_s[tid] = acc * (1.0f / 128.0f);
    }
    __syncthreads();

    // ---- A fragments from g_s: 8 diagonal classes, 3 words (w == x) ----
    uint32_t ax[8], ay[8], az[8];
#pragma unroll
    for (int i = 0; i < 8; i++) {
        int cls = ((warp_m * 2) + i) & 7;
        int d0 = (16 * cls + (lane >> 2) - 2 * (lane & 3)) & 127;
        ax[i] = pack_f16x2(g_s[d0], g_s[(d0 - 1) & 127]);
        int d1 = (d0 + 8) & 127;
        ay[i] = pack_f16x2(g_s[d1], g_s[(d1 - 1) & 127]);
        int d2 = (d0 - 8) & 127;
        az[i] = pack_f16x2(g_s[d2], g_s[(d2 - 1) & 127]);
    }

    // convert constants: thread -> (n-row n0, k-eighth kq)
    const int n0 = tid & 63;
    const int kq = tid >> 6;                 // 0..7 (16 k's each)
    const int nn = n0 & 15;
    const int gam = 4 * ((nn >> 1) & 3) + 2 * ((nn >> 3) & 1) + (nn & 1);
    const int src_col = (n0 & ~15) + gam;    // permuted staging column

    // ldsm constants (fp16 buf rows = n, 64 rows, pitch 272)
    const uint32_t lm_off = ((lane & 7) + ((lane >> 4) << 3)) * XPITCH_B
                          + ((lane >> 3) & 1) * 16
                          + (uint32_t)warp_n * 16 * XPITCH_B;

    // one chunk = 8 k-rows of this thread's (n0, kq) slice
#define CONVERT_CHUNK(ch, sk_, dk_)                                          \
    do {                                                                     \
        float v_[8];                                                         \
        _Pragma("unroll")                                                    \
        for (int ii_ = 0; ii_ < 8; ii_++)                                    \
            v_[ii_] = *reinterpret_cast<const float*>(                       \
                (sk_) + (size_t)((ch) * 8 + ii_) * SPITCH_B);                \
        uint4 hq_;                                                           \
        hq_.x = pack_f16x2(v_[0], v_[1]);                                    \
        hq_.y = pack_f16x2(v_[2], v_[3]);                                    \
        hq_.z = pack_f16x2(v_[4], v_[5]);                                    \
        hq_.w = pack_f16x2(v_[6], v_[7]);                                    \
        *reinterpret_cast<uint4*>((dk_) + (ch) * 16) = hq_;                  \
    } while (0)

    // ---- prologue: convert tile0 (serial), stage tile1 ----
    cp_wait0();
    __syncthreads();
    {
        const char* sk = smc + SMEM_S0 + src_col * 4
                       + (size_t)(kq * 16) * SPITCH_B;
        char* dk = smc + SMEM_F0 + (uint32_t)n0 * XPITCH_B + kq * 32;
        CONVERT_CHUNK(0, sk, dk);
        CONVERT_CHUNK(1, sk, dk);
    }
    __syncthreads();                   // stg0 reads done; f16[0] visible
    {
        const int t1 = tile + stride;
        if (t1 < NTILES_TOTAL) STAGE_TILE(t1, smb + SMEM_S1);
        cp_commit();                   // group: t1
    }

    int par = 0;
    // invariant at loop top: f16[par] = tile t (visible to all);
    // stg[par^1] carries cp(t+1) (committed); stg[par] free.
    for (; tile < NTILES_TOTAL; tile += stride, par ^= 1) {
        // 1. issue cp(t+2) into the free staging buffer stg[par]
        {
            const int n2 = tile + 2 * stride;
            if (n2 < NTILES_TOTAL)
                STAGE_TILE(n2, smb + (par ? SMEM_S1 : SMEM_S0));
            cp_commit();
        }

        // 2. cp(t+1) landed (covered by previous iteration's work)
        cp_wait1();
        __syncthreads();

        // 3. fused: mma(t) from f16[par] + convert(t+1) stg[par^1]->f16[par^1]
        const bool hn = (tile + stride) < NTILES_TOTAL;
        {
            const char* csk = smc + (par ? SMEM_S0 : SMEM_S1) + src_col * 4
                            + (size_t)(kq * 16) * SPITCH_B;
            char* cdk = smc + (par ? SMEM_F0 : SMEM_F1)
                      + (uint32_t)n0 * XPITCH_B + kq * 32;
            const uint32_t xh_base = smb + (par ? SMEM_F1 : SMEM_F0) + lm_off;

            float acc[2][2][4];
#pragma unroll
            for (int mt = 0; mt < 2; mt++)
#pragma unroll
                for (int nt = 0; nt < 2; nt++)
#pragma unroll
                    for (int r = 0; r < 4; r++) acc[mt][nt][r] = 0.0f;

#pragma unroll
            for (int ks = 0; ks < 8; ks++) {
                uint32_t b0, b1, b2, b3;
                ldsm_x4(b0, b1, b2, b3, xh_base + (uint32_t)ks * 32);
#pragma unroll
                for (int mt = 0; mt < 2; mt++) {
                    const int ai = (mt - ks) & 7;
                    mma16816(acc[mt][0], ax[ai], ay[ai], az[ai], b0, b1);
                    mma16816(acc[mt][1], ax[ai], ay[ai], az[ai], b2, b3);
                }
                if (ks == 2 && hn) CONVERT_CHUNK(0, csk, cdk);
                if (ks == 6 && hn) CONVERT_CHUNK(1, csk, cdk);
            }

            // epilogue: lane holds cols [4q,4q+4) of rows m0, m0+8
            float* yb = y + (size_t)(tile >> 6) * CCH * HWSZ
                          + (tile & 63) * NTILE_N + warp_n * 16
                          + 4 * (lane & 3);
#pragma unroll
            for (int mt = 0; mt < 2; mt++) {
                int m0 = warp_m * 32 + mt * 16 + (lane >> 2);
                *reinterpret_cast<float4*>(yb + (size_t)m0 * HWSZ) =
                    make_float4(acc[mt][0][0], acc[mt][0][1],
                                acc[mt][1][0], acc[mt][1][1]);
                *reinterpret_cast<float4*>(yb + (size_t)(m0 + 8) * HWSZ) =
                    make_float4(acc[mt][0][2], acc[mt][0][3],
                                acc[mt][1][2], acc[mt][1][3]);
            }
        }

        // 4. f16[par^1] complete for all; stg[par^1] reads done
        __syncthreads();
    }
#undef STAGE_TILE
#undef CONVERT_CHUNK
}

// ---------------------------------------------------------------------------
extern "C" void kernel_launch(void* const* d_in, const int* in_sizes, int n_in,
                              void* d_out, int out_size) {
    const float* act  = (const float*)d_in[0];
    const float* filt = (const float*)d_in[1];
    if (n_in >= 2 && in_sizes[0] == SCOPE) {
        act  = (const float*)d_in[1];
        filt = (const float*)d_in[0];
    }
    float* out = (float*)d_out;

    int nsm = 148;
    cudaDeviceGetAttribute(&nsm, cudaDevAttrMultiProcessorCount, 0);
    int grid = 2 * nsm;
    if (grid > NTILES_TOTAL) grid = NTILES_TOTAL;

    cudaFuncSetAttribute(gemm_mma,
                         cudaFuncAttributeMaxDynamicSharedMemorySize, SMEM_DYN);
    gemm_mma<<<grid, NTHREADS, SMEM_DYN>>>(act, filt, out);
}